// round 5
// baseline (speedup 1.0000x reference)
#include <cuda_runtime.h>
#include <cuda_bf16.h>
#include <math.h>

// Problem constants
#define B_   128
#define T_   2048
#define F_   512
#define OS_  20
#define OF_  42
#define NC_  10
#define NCHUNK_ 8
#define CHUNK_  256   // NCHUNK_*CHUNK_ == T_
#define NCOL_ (B_ * OS_)   // 2560

// -------- device scratch (no allocation allowed) --------
__device__ float g_partial[B_ * NCHUNK_ * F_];   // 2 MB
__device__ float g_xT[NCOL_ * F_];               // [col=b*20+j][f]
__device__ float g_act[OF_ * NCOL_];             // c1: [row][col]
__device__ float g_bns[B_ * F_];
__device__ float g_bnss[B_ * F_];
__device__ float g_scale[F_];
__device__ float g_shift[F_];

// ============================================================
// Kernel 1: partial column sums of y over t in [chunk] ∩ [0, fs)
// ============================================================
__global__ void k_pool_partial(const float* __restrict__ y,
                               const int*   __restrict__ lengths) {
    const int c = blockIdx.x;
    const int b = blockIdx.y;
    const int tid = threadIdx.x;

    const int fs = lengths[b] - (OS_ - 1);
    int t0 = c * CHUNK_;
    int t1 = min(t0 + CHUNK_, fs);

    const float4* row = reinterpret_cast<const float4*>(y + (size_t)b * T_ * F_);
    const int rstride = F_ / 4;

    float4 acc = make_float4(0.f, 0.f, 0.f, 0.f);
    int t = t0;
    for (; t + 8 <= t1; t += 8) {
        float4 v0 = __ldcs(&row[(t + 0) * rstride + tid]);
        float4 v1 = __ldcs(&row[(t + 1) * rstride + tid]);
        float4 v2 = __ldcs(&row[(t + 2) * rstride + tid]);
        float4 v3 = __ldcs(&row[(t + 3) * rstride + tid]);
        float4 v4 = __ldcs(&row[(t + 4) * rstride + tid]);
        float4 v5 = __ldcs(&row[(t + 5) * rstride + tid]);
        float4 v6 = __ldcs(&row[(t + 6) * rstride + tid]);
        float4 v7 = __ldcs(&row[(t + 7) * rstride + tid]);
        acc.x += v0.x; acc.y += v0.y; acc.z += v0.z; acc.w += v0.w;
        acc.x += v1.x; acc.y += v1.y; acc.z += v1.z; acc.w += v1.w;
        acc.x += v2.x; acc.y += v2.y; acc.z += v2.z; acc.w += v2.w;
        acc.x += v3.x; acc.y += v3.y; acc.z += v3.z; acc.w += v3.w;
        acc.x += v4.x; acc.y += v4.y; acc.z += v4.z; acc.w += v4.w;
        acc.x += v5.x; acc.y += v5.y; acc.z += v5.z; acc.w += v5.w;
        acc.x += v6.x; acc.y += v6.y; acc.z += v6.z; acc.w += v6.w;
        acc.x += v7.x; acc.y += v7.y; acc.z += v7.z; acc.w += v7.w;
    }
    for (; t < t1; ++t) {
        float4 v = __ldcs(&row[t * rstride + tid]);
        acc.x += v.x; acc.y += v.y; acc.z += v.z; acc.w += v.w;
    }

    float4* out = reinterpret_cast<float4*>(g_partial + (size_t)(b * NCHUNK_ + c) * F_);
    out[tid] = acc;
}

// ============================================================
// Kernel 2: finish pooling + transpose + BN partials.
// ============================================================
__global__ void __launch_bounds__(512, 1)
k_pool_finish(const float* __restrict__ y,
              const int*   __restrict__ lengths) {
    __shared__ float sm[F_ * 21];

    const int b = blockIdx.x;
    const int f = threadIdx.x;

    const int fs = lengths[b] - (OS_ - 1);
    const float inv = 1.0f / (float)fs;

    float base = 0.f;
#pragma unroll
    for (int c = 0; c < NCHUNK_; ++c)
        base += g_partial[(size_t)(b * NCHUNK_ + c) * F_ + f];

    const float* yb = y + (size_t)b * T_ * F_ + f;

    float run = base;
    float s = 0.f, ss = 0.f;
    {
        float v = run * inv;
        sm[f * 21 + 0] = v;
        s += v; ss = fmaf(v, v, ss);
    }
#pragma unroll
    for (int j = 1; j < OS_; ++j) {
        run += yb[(size_t)(fs + j - 1) * F_] - yb[(size_t)(j - 1) * F_];
        float v = run * inv;
        sm[f * 21 + j] = v;
        s += v; ss = fmaf(v, v, ss);
    }
    g_bns [b * F_ + f] = s;
    g_bnss[b * F_ + f] = ss;
    __syncthreads();

#pragma unroll
    for (int j = 0; j < OS_; ++j)
        g_xT[(size_t)(b * OS_ + j) * F_ + f] = sm[f * 21 + j];
}

// ============================================================
// Kernel 3: BN stats reduce -> fused scale/shift.
// ============================================================
__global__ void k_bnstats(const float* __restrict__ gamma,
                          const float* __restrict__ beta) {
    const int f = blockIdx.x;
    const int b = threadIdx.x;

    __shared__ float s1[128];
    __shared__ float s2[128];

    s1[b] = g_bns [b * F_ + f];
    s2[b] = g_bnss[b * F_ + f];
    __syncthreads();
    for (int off = 64; off > 0; off >>= 1) {
        if (b < off) { s1[b] += s1[b + off]; s2[b] += s2[b + off]; }
        __syncthreads();
    }
    if (b == 0) {
        const float n = (float)(B_ * OS_);
        float mu = s1[0] / n;
        float var = s2[0] / n - mu * mu;
        float sc = gamma[f] * rsqrtf(var + 1e-5f);
        g_scale[f] = sc;
        g_shift[f] = beta[f] - mu * sc;
    }
}

// ============================================================
// Kernel 4: layer 1 GEMM [42 x 512 x 2560].
// grid 160, block 224 = (ty 0..13) x (tx 0..15).
// thread: rows {ty, ty+14, ty+28}, col = blk*16+tx.
// smem: ws[42][520], xs[16][520] (k-stride 520 words).
// ============================================================
#define L1_KS 520
#define L1_WFL (OF_ * L1_KS)               // 21840
#define L1_FLOATS (L1_WFL + 16 * L1_KS)    // 30160

__global__ void __launch_bounds__(224, 1)
k_l1(const float* __restrict__ W1, const float* __restrict__ b1) {
    extern __shared__ float sm[];
    float* ws = sm;                // [42][520]
    float* xs = sm + L1_WFL;       // [16][520]

    const int tid = threadIdx.x;
    const int tx  = tid & 15;
    const int ty  = tid >> 4;      // 0..13
    const int col0 = blockIdx.x * 16;

    // stage W1: 42*128 float4
    {
        const float4* wg = reinterpret_cast<const float4*>(W1);
        float4* wsm = reinterpret_cast<float4*>(ws);
        for (int id = tid; id < OF_ * 128; id += 224) {
            int r = id >> 7, kq = id & 127;
            wsm[r * 130 + kq] = wg[r * 128 + kq];
        }
    }
    // stage x (BN applied): 16*128 float4
    {
        const float4* sc4 = reinterpret_cast<const float4*>(g_scale);
        const float4* sh4 = reinterpret_cast<const float4*>(g_shift);
        float4* xsm = reinterpret_cast<float4*>(xs);
        for (int id = tid; id < 16 * 128; id += 224) {
            int c = id >> 7, kq = id & 127;
            float4 v = *reinterpret_cast<const float4*>(
                g_xT + (size_t)(col0 + c) * F_ + 4 * kq);
            float4 s = sc4[kq];
            float4 h = sh4[kq];
            float4 o;
            o.x = fmaf(v.x, s.x, h.x);
            o.y = fmaf(v.y, s.y, h.y);
            o.z = fmaf(v.z, s.z, h.z);
            o.w = fmaf(v.w, s.w, h.w);
            xsm[c * 130 + kq] = o;
        }
    }
    __syncthreads();

    const float4* w0 = reinterpret_cast<const float4*>(ws) + (ty     ) * 130;
    const float4* w1 = reinterpret_cast<const float4*>(ws) + (ty + 14) * 130;
    const float4* w2 = reinterpret_cast<const float4*>(ws) + (ty + 28) * 130;
    const float4* xp = reinterpret_cast<const float4*>(xs) + tx * 130;

    float a0 = 0.f, a1 = 0.f, a2 = 0.f;
    float e0 = 0.f, e1 = 0.f, e2 = 0.f;
#pragma unroll 4
    for (int kq = 0; kq < 128; kq += 2) {
        float4 xv = xp[kq];
        float4 u0 = w0[kq];
        float4 u1 = w1[kq];
        float4 u2 = w2[kq];
        a0 = fmaf(u0.x, xv.x, a0); a0 = fmaf(u0.y, xv.y, a0);
        a0 = fmaf(u0.z, xv.z, a0); a0 = fmaf(u0.w, xv.w, a0);
        a1 = fmaf(u1.x, xv.x, a1); a1 = fmaf(u1.y, xv.y, a1);
        a1 = fmaf(u1.z, xv.z, a1); a1 = fmaf(u1.w, xv.w, a1);
        a2 = fmaf(u2.x, xv.x, a2); a2 = fmaf(u2.y, xv.y, a2);
        a2 = fmaf(u2.z, xv.z, a2); a2 = fmaf(u2.w, xv.w, a2);
        float4 yv = xp[kq + 1];
        float4 t0 = w0[kq + 1];
        float4 t1 = w1[kq + 1];
        float4 t2 = w2[kq + 1];
        e0 = fmaf(t0.x, yv.x, e0); e0 = fmaf(t0.y, yv.y, e0);
        e0 = fmaf(t0.z, yv.z, e0); e0 = fmaf(t0.w, yv.w, e0);
        e1 = fmaf(t1.x, yv.x, e1); e1 = fmaf(t1.y, yv.y, e1);
        e1 = fmaf(t1.z, yv.z, e1); e1 = fmaf(t1.w, yv.w, e1);
        e2 = fmaf(t2.x, yv.x, e2); e2 = fmaf(t2.y, yv.y, e2);
        e2 = fmaf(t2.z, yv.z, e2); e2 = fmaf(t2.w, yv.w, e2);
    }
    a0 += e0; a1 += e1; a2 += e2;

    const int col = col0 + tx;
    g_act[(size_t)(ty     ) * NCOL_ + col] = fmaxf(a0 + b1[ty     ], 0.f);
    g_act[(size_t)(ty + 14) * NCOL_ + col] = fmaxf(a1 + b1[ty + 14], 0.f);
    g_act[(size_t)(ty + 28) * NCOL_ + col] = fmaxf(a2 + b1[ty + 28], 0.f);
}

// ============================================================
// Kernel 5: layers 2..5 + head + softmax. block = batch, 160 thr.
// thread: 6 rows {ty+8i} x col tx (ty=tid/20 in 0..7, tx=tid%20).
// Weights staged zero-padded to 48 rows; broadcast W reads.
// smem floats: db[20][212] | ws[20736] | lg[16]
// ============================================================
#define R_DBS 212
#define R_DB  (OS_ * R_DBS)        // 4240
#define R_W2  0
#define R_W3  (48 * 44)            // 2112
#define R_W4  (R_W3 + 48 * 84)     // 6144
#define R_W5  (R_W4 + 48 * 132)    // 12480
#define R_WTOT (R_W5 + 48 * 172)   // 20736
#define R_FLOATS (R_DB + R_WTOT + 16)   // 24992

__device__ __forceinline__ void rest_layer(const float* __restrict__ bg,
                                           float* db, const float* wsl,
                                           int S, int INP, int OB,
                                           int tx, int ty) {
    float a[6] = {0.f, 0.f, 0.f, 0.f, 0.f, 0.f};
    const float* xc = db + tx * R_DBS;
    for (int i4 = 0; i4 < INP; i4 += 4) {
        float4 xv = *reinterpret_cast<const float4*>(xc + i4);
#pragma unroll
        for (int rr = 0; rr < 6; ++rr) {
            float4 wv = *reinterpret_cast<const float4*>(wsl + (ty + 8 * rr) * S + i4);
            a[rr] = fmaf(wv.x, xv.x, a[rr]);
            a[rr] = fmaf(wv.y, xv.y, a[rr]);
            a[rr] = fmaf(wv.z, xv.z, a[rr]);
            a[rr] = fmaf(wv.w, xv.w, a[rr]);
        }
    }
    __syncthreads();   // all reads of db done before writes
#pragma unroll
    for (int rr = 0; rr < 6; ++rr) {
        int r = ty + 8 * rr;
        if (r < OF_)
            db[tx * R_DBS + OB + r] = fmaxf(a[rr] + bg[r], 0.f);
    }
    __syncthreads();
}

__global__ void __launch_bounds__(160, 1)
k_rest(const float* __restrict__ W2, const float* __restrict__ b2,
       const float* __restrict__ W3, const float* __restrict__ b3,
       const float* __restrict__ W4, const float* __restrict__ b4,
       const float* __restrict__ W5, const float* __restrict__ b5,
       const float* __restrict__ Wlin, const float* __restrict__ blin,
       float* __restrict__ out) {
    extern __shared__ float sm[];
    float* db = sm;                // [j 20][chan stride 212]
    float* ws = sm + R_DB;
    float* lg = sm + R_DB + R_WTOT;

    const int tid  = threadIdx.x;
    const int lane = tid & 31;
    const int warp = tid >> 5;     // 0..4
    const int tx   = tid % 20;
    const int ty   = tid / 20;     // 0..7
    const int b    = blockIdx.x;

    for (int i = tid; i < R_FLOATS; i += 160) sm[i] = 0.f;
    __syncthreads();

    // stage c1 into db (chan 0..41)
    for (int idx = tid; idx < OF_ * OS_; idx += 160) {
        int chan = idx / OS_;
        int j = idx - chan * OS_;
        db[j * R_DBS + chan] = g_act[(size_t)chan * NCOL_ + b * OS_ + j];
    }
    // stage weights, zero-padded rows/cols
    for (int idx = tid; idx < OF_ * 42; idx += 160) {
        int o = idx / 42, i = idx - o * 42;
        ws[R_W2 + o * 44 + i] = W2[idx];
    }
    for (int idx = tid; idx < OF_ * 84; idx += 160) {
        int o = idx / 84, i = idx - o * 84;
        ws[R_W3 + o * 84 + i] = W3[idx];
    }
    for (int idx = tid; idx < OF_ * 126; idx += 160) {
        int o = idx / 126, i = idx - o * 126;
        ws[R_W4 + o * 132 + i] = W4[idx];
    }
    for (int idx = tid; idx < OF_ * 168; idx += 160) {
        int o = idx / 168, i = idx - o * 168;
        ws[R_W5 + o * 172 + i] = W5[idx];
    }
    __syncthreads();

    rest_layer(b2, db, ws + R_W2,  44,  44,  42, tx, ty);
    rest_layer(b3, db, ws + R_W3,  84,  84,  84, tx, ty);
    rest_layer(b4, db, ws + R_W4, 132, 128, 126, tx, ty);
    rest_layer(b5, db, ws + R_W5, 172, 168, 168, tx, ty);

    // head: warp w -> classes 2w, 2w+1; flat k = ch*20 + j
    {
        const int n0 = warp * 2;
        const int n1 = n0 + 1;
        const float* wl0 = Wlin + (size_t)n0 * (210 * OS_);
        const float* wl1 = Wlin + (size_t)n1 * (210 * OS_);
        float a0 = 0.f, a1 = 0.f;
        for (int k = lane; k < 210 * OS_; k += 32) {
            int ch = k / OS_;
            int j  = k - ch * OS_;
            float v = db[j * R_DBS + ch];
            a0 = fmaf(wl0[k], v, a0);
            a1 = fmaf(wl1[k], v, a1);
        }
#pragma unroll
        for (int off = 16; off > 0; off >>= 1) {
            a0 += __shfl_xor_sync(0xffffffffu, a0, off);
            a1 += __shfl_xor_sync(0xffffffffu, a1, off);
        }
        if (lane == 0) { lg[n0] = a0 + blin[n0]; lg[n1] = a1 + blin[n1]; }
    }
    __syncthreads();

    if (tid == 0) {
        float m = lg[0];
#pragma unroll
        for (int n = 1; n < NC_; ++n) m = fmaxf(m, lg[n]);
        float e[NC_], s = 0.f;
#pragma unroll
        for (int n = 0; n < NC_; ++n) { e[n] = __expf(lg[n] - m); s += e[n]; }
        float invs = 1.f / s;
#pragma unroll
        for (int n = 0; n < NC_; ++n) out[b * NC_ + n] = e[n] * invs;
    }
}

// ============================================================
extern "C" void kernel_launch(void* const* d_in, const int* in_sizes, int n_in,
                              void* d_out, int out_size) {
    const float* y       = (const float*)d_in[0];
    const int*   lengths = (const int*)  d_in[1];
    const float* gamma   = (const float*)d_in[2];
    const float* beta    = (const float*)d_in[3];
    const float* W1 = (const float*)d_in[4];
    const float* b1 = (const float*)d_in[5];
    const float* W2 = (const float*)d_in[6];
    const float* b2 = (const float*)d_in[7];
    const float* W3 = (const float*)d_in[8];
    const float* b3 = (const float*)d_in[9];
    const float* W4 = (const float*)d_in[10];
    const float* b4 = (const float*)d_in[11];
    const float* W5 = (const float*)d_in[12];
    const float* b5 = (const float*)d_in[13];
    const float* Wlin = (const float*)d_in[14];
    const float* blin = (const float*)d_in[15];
    float* out = (float*)d_out;

    const size_t l1_smem = (size_t)L1_FLOATS * sizeof(float);   // ~120.6 KB
    const size_t rs_smem = (size_t)R_FLOATS * sizeof(float);    // ~100 KB
    cudaFuncSetAttribute(k_l1, cudaFuncAttributeMaxDynamicSharedMemorySize,
                         (int)l1_smem);
    cudaFuncSetAttribute(k_rest, cudaFuncAttributeMaxDynamicSharedMemorySize,
                         (int)rs_smem);

    dim3 g1(NCHUNK_, B_);
    k_pool_partial<<<g1, 128>>>(y, lengths);
    k_pool_finish<<<B_, 512>>>(y, lengths);
    k_bnstats<<<F_, 128>>>(gamma, beta);
    k_l1<<<160, 224, l1_smem>>>(W1, b1);
    k_rest<<<B_, 160, rs_smem>>>(W2, b2, W3, b3, W4, b4, W5, b5,
                                 Wlin, blin, out);
}